// round 2
// baseline (speedup 1.0000x reference)
#include <cuda_runtime.h>
#include <math.h>

// Sampler: Gumbel-keys relaxed top-k. khot = sum_{t=1..k} softmax(att_g_t),
// att_g_{t+1} = att_g_t + log(max(1 - onehot_t, eps)).
// One CTA per row (B=128 rows, n=1024). All state in registers; one
// __syncthreads per step via single-pass online-softmax (m,s) reduction.

#define NTHREADS 256
#define NWARPS   (NTHREADS / 32)
#define NNODES   1024
#define EPT      (NNODES / NTHREADS)   // elements per thread = 4
#define EPS_F    1.1754943508222875e-38f  // np.finfo(float32).tiny

__global__ __launch_bounds__(NTHREADS, 1)
void sampler_topk_kernel(const float* __restrict__ att,
                         const float* __restrict__ uni,
                         const int*  __restrict__ kptr,
                         float* __restrict__ out)
{
    // double-buffered per-warp (m,s) slots: one barrier per iteration is safe
    __shared__ float sm_m[2][NWARPS];
    __shared__ float sm_s[2][NWARPS];

    const int row  = blockIdx.x;
    const int tid  = threadIdx.x;
    const int lane = tid & 31;
    const int warp = tid >> 5;
    const int k    = *kptr;

    const float* __restrict__ arow = att + row * NNODES;
    const float* __restrict__ urow = uni + row * NNODES;
    float*       __restrict__ orow = out + row * NNODES;

    float att_g[EPT], acc[EPT], e[EPT];

    // Gumbel init: att_g = att - log(-log(u + eps))  (accurate logf, runs once)
    #pragma unroll
    for (int j = 0; j < EPT; ++j) {
        const int idx = tid + j * NTHREADS;       // coalesced
        float u = urow[idx];
        float g = -logf(-logf(u + EPS_F));
        att_g[j] = arow[idx] + g;
        acc[j] = 0.0f;
        e[j]   = 0.0f;
    }
    float scale = 0.0f;   // onehot_{-1} = 0

    for (int t = 0; t < k; ++t) {
        // ---- phase A: materialize previous onehot, accumulate, suppress ----
        float m = -3.402823466e38f;
        #pragma unroll
        for (int j = 0; j < EPT; ++j) {
            float oh = e[j] * scale;              // onehot_{t-1}
            acc[j] += oh;
            att_g[j] += __logf(fmaxf(1.0f - oh, EPS_F));
            m = fmaxf(m, att_g[j]);
        }
        // ---- phase B: local exps + sum (stable wrt thread-local max) ----
        float s = 0.0f;
        #pragma unroll
        for (int j = 0; j < EPT; ++j) {
            e[j] = __expf(att_g[j] - m);
            s += e[j];
        }
        const float m_local = m;   // e[] is normalized against THIS max
        // ---- warp-level (m,s) pair reduce; bfly -> all lanes hold result ----
        #pragma unroll
        for (int o = 16; o > 0; o >>= 1) {
            float mo = __shfl_xor_sync(0xffffffffu, m, o);
            float so = __shfl_xor_sync(0xffffffffu, s, o);
            float mn = fmaxf(m, mo);
            s = s * __expf(m - mn) + so * __expf(mo - mn);
            m = mn;
        }
        // ---- cross-warp: one barrier, then redundant tree combine ----
        const int buf = t & 1;
        if (lane == 0) { sm_m[buf][warp] = m; sm_s[buf][warp] = s; }
        __syncthreads();
        float Ms[NWARPS], Ss[NWARPS];
        #pragma unroll
        for (int w = 0; w < NWARPS; ++w) {
            Ms[w] = sm_m[buf][w];
            Ss[w] = sm_s[buf][w];
        }
        #pragma unroll
        for (int step = 1; step < NWARPS; step <<= 1) {
            #pragma unroll
            for (int w = 0; w + step < NWARPS; w += 2 * step) {
                float mn = fmaxf(Ms[w], Ms[w + step]);
                Ss[w] = Ss[w] * __expf(Ms[w] - mn)
                      + Ss[w + step] * __expf(Ms[w + step] - mn);
                Ms[w] = mn;
            }
        }
        // onehot_j = e_j * exp(m_local - M_block) / S_block
        scale = __fdividef(__expf(m_local - Ms[0]), Ss[0]);
    }

    // accumulate last step's onehot and write out
    #pragma unroll
    for (int j = 0; j < EPT; ++j) {
        acc[j] += e[j] * scale;
        orow[tid + j * NTHREADS] = acc[j];
    }
}

extern "C" void kernel_launch(void* const* d_in, const int* in_sizes, int n_in,
                              void* d_out, int out_size)
{
    const float* att = (const float*)d_in[0];
    const float* uni = (const float*)d_in[1];
    const int*   kp  = (const int*)d_in[2];
    float* out = (float*)d_out;

    const int B = in_sizes[0] / NNODES;   // 128
    sampler_topk_kernel<<<B, NTHREADS>>>(att, uni, kp, out);
}

// round 3
// speedup vs baseline: 1.1450x; 1.1450x over previous
#include <cuda_runtime.h>
#include <math.h>

// Sampler: Gumbel-keys relaxed top-k. khot = sum_{t=1..k} softmax(att_g_t),
// att_g_{t+1} = att_g_t + log(max(1 - onehot_t, eps)).
// One CTA per row (B=128 rows, n=1024). All state in registers.
// Two-phase (max, then sum) block reduction so each element is
// exponentiated exactly once per step -> 9 MUFU ops/thread/step.

#define NTHREADS 256
#define NWARPS   (NTHREADS / 32)
#define NNODES   1024
#define EPT      (NNODES / NTHREADS)   // 4
#define EPS_F    1.1754943508222875e-38f  // np.finfo(float32).tiny

__global__ __launch_bounds__(NTHREADS, 1)
void sampler_topk_kernel(const float* __restrict__ att,
                         const float* __restrict__ uni,
                         const int*  __restrict__ kptr,
                         float* __restrict__ out)
{
    // sm_m protected by bar2 (reads before bar2[t], writes after bar2[t]);
    // sm_s protected by bar1[t+1]. No double buffering needed.
    __shared__ __align__(16) float sm_m[NWARPS];
    __shared__ __align__(16) float sm_s[NWARPS];

    const int row  = blockIdx.x;
    const int tid  = threadIdx.x;
    const int lane = tid & 31;
    const int warp = tid >> 5;
    const int k    = *kptr;

    const float* __restrict__ arow = att + row * NNODES;
    const float* __restrict__ urow = uni + row * NNODES;
    float*       __restrict__ orow = out + row * NNODES;

    float att_g[EPT], acc[EPT], e[EPT];

    // Gumbel init: att_g = att - log(-log(u + eps))  (accurate logf, once)
    #pragma unroll
    for (int j = 0; j < EPT; ++j) {
        const int idx = tid + j * NTHREADS;       // coalesced
        float u = urow[idx];
        att_g[j] = arow[idx] - logf(-logf(u + EPS_F));
        acc[j] = 0.0f;
        e[j]   = 0.0f;
    }
    float scale = 0.0f;   // onehot_{-1} = 0

    for (int t = 0; t < k; ++t) {
        // ---- phase A: fold in previous onehot, suppress, local max ----
        float m = -3.402823466e38f;
        #pragma unroll
        for (int j = 0; j < EPT; ++j) {
            float oh = e[j] * scale;              // onehot_{t-1}
            acc[j] += oh;
            att_g[j] += __logf(fmaxf(1.0f - oh, EPS_F));
            m = fmaxf(m, att_g[j]);
        }
        // ---- warp max (ALU only) ----
        #pragma unroll
        for (int o = 16; o > 0; o >>= 1)
            m = fmaxf(m, __shfl_xor_sync(0xffffffffu, m, o));
        if (lane == 0) sm_m[warp] = m;
        __syncthreads();                           // bar1
        // block max from 8 per-warp values (vectorized broadcast loads)
        float4 m0 = *(const float4*)&sm_m[0];
        float4 m1 = *(const float4*)&sm_m[4];
        float M = fmaxf(fmaxf(fmaxf(m0.x, m0.y), fmaxf(m0.z, m0.w)),
                        fmaxf(fmaxf(m1.x, m1.y), fmaxf(m1.z, m1.w)));
        // ---- phase B: exps against block max (the only EX2s), local sum ----
        float s = 0.0f;
        #pragma unroll
        for (int j = 0; j < EPT; ++j) {
            e[j] = __expf(att_g[j] - M);
            s += e[j];
        }
        // ---- warp sum (ALU only) ----
        #pragma unroll
        for (int o = 16; o > 0; o >>= 1)
            s += __shfl_xor_sync(0xffffffffu, s, o);
        if (lane == 0) sm_s[warp] = s;
        __syncthreads();                           // bar2
        float4 s0 = *(const float4*)&sm_s[0];
        float4 s1 = *(const float4*)&sm_s[4];
        float S = (s0.x + s0.y) + (s0.z + s0.w)
                + (s1.x + s1.y) + (s1.z + s1.w);
        scale = __fdividef(1.0f, S);               // onehot_j = e[j] * scale
    }

    // accumulate last step's onehot and write out
    #pragma unroll
    for (int j = 0; j < EPT; ++j) {
        acc[j] += e[j] * scale;
        orow[tid + j * NTHREADS] = acc[j];
    }
}

extern "C" void kernel_launch(void* const* d_in, const int* in_sizes, int n_in,
                              void* d_out, int out_size)
{
    const float* att = (const float*)d_in[0];
    const float* uni = (const float*)d_in[1];
    const int*   kp  = (const int*)d_in[2];
    float* out = (float*)d_out;

    const int B = in_sizes[0] / NNODES;   // 128
    sampler_topk_kernel<<<B, NTHREADS>>>(att, uni, kp, out);
}

// round 4
// speedup vs baseline: 1.8339x; 1.6017x over previous
#include <cuda_runtime.h>
#include <math.h>

// Sampler: Gumbel-keys relaxed top-k. khot = sum_{t=1..k} softmax(att_g_t),
// att_g_{t+1} = att_g_t + log(max(1 - onehot_t, eps)).
// One CTA per row (B=128 rows, n=1024), state in registers.
// KEY: att_g is monotone non-increasing -> block max M0 computed ONCE
// before the loop is a valid (shift-invariant) softmax shift for all steps.
// Per step: only a SUM reduction (1 shfl chain + 1 barrier). Log2 domain
// so suppression/exp are raw MUFU lg2/ex2.

#define NTHREADS 256
#define NWARPS   (NTHREADS / 32)
#define NNODES   1024
#define EPT      (NNODES / NTHREADS)   // 4
#define EPS_F    1.1754943508222875e-38f  // np.finfo(float32).tiny
#define LOG2E    1.4426950408889634f

__device__ __forceinline__ float ex2_approx(float x) {
    float r; asm("ex2.approx.f32 %0, %1;" : "=f"(r) : "f"(x)); return r;
}
__device__ __forceinline__ float lg2_approx(float x) {
    float r; asm("lg2.approx.f32 %0, %1;" : "=f"(r) : "f"(x)); return r;
}

__global__ __launch_bounds__(NTHREADS, 1)
void sampler_topk_kernel(const float* __restrict__ att,
                         const float* __restrict__ uni,
                         const int*  __restrict__ kptr,
                         float* __restrict__ out)
{
    __shared__ __align__(16) float sm_s[2][NWARPS];  // double-buffered sums
    __shared__ __align__(16) float sm_m[NWARPS];     // init-time max only

    const int row  = blockIdx.x;
    const int tid  = threadIdx.x;
    const int lane = tid & 31;
    const int warp = tid >> 5;
    const int k    = *kptr;

    const float* __restrict__ arow = att + row * NNODES;
    const float* __restrict__ urow = uni + row * NNODES;
    float*       __restrict__ orow = out + row * NNODES;

    float b[EPT], acc[EPT], e[EPT];

    // Gumbel init in log2 domain: b = (att - log(-log(u+eps))) * log2(e)
    float m = -3.402823466e38f;
    #pragma unroll
    for (int j = 0; j < EPT; ++j) {
        const int idx = tid + j * NTHREADS;          // coalesced
        float u = urow[idx];
        b[j] = (arow[idx] - logf(-logf(u + EPS_F))) * LOG2E;
        m = fmaxf(m, b[j]);
        acc[j] = 0.0f;
        e[j]   = 0.0f;
    }
    // one-time block max M0 (valid shift forever: b only decreases)
    #pragma unroll
    for (int o = 16; o > 0; o >>= 1)
        m = fmaxf(m, __shfl_xor_sync(0xffffffffu, m, o));
    if (lane == 0) sm_m[warp] = m;
    __syncthreads();
    {
        float4 m0 = *(const float4*)&sm_m[0];
        float4 m1 = *(const float4*)&sm_m[4];
        float M = fmaxf(fmaxf(fmaxf(m0.x, m0.y), fmaxf(m0.z, m0.w)),
                        fmaxf(fmaxf(m1.x, m1.y), fmaxf(m1.z, m1.w)));
        #pragma unroll
        for (int j = 0; j < EPT; ++j) b[j] -= M;     // pre-shifted
    }
    float scale = 0.0f;   // onehot_{-1} = 0

    for (int t = 0; t < k; ++t) {
        float s = 0.0f;
        #pragma unroll
        for (int j = 0; j < EPT; ++j) {
            float oh = e[j] * scale;                 // onehot_{t-1}
            acc[j] += oh;
            b[j] += lg2_approx(fmaxf(1.0f - oh, EPS_F));  // log2(khot_mask)
            e[j] = ex2_approx(b[j]);                 // exp(att_g - M0)
            s += e[j];
        }
        // warp sum (ALU only)
        #pragma unroll
        for (int o = 16; o > 0; o >>= 1)
            s += __shfl_xor_sync(0xffffffffu, s, o);
        const int buf = t & 1;
        if (lane == 0) sm_s[buf][warp] = s;
        __syncthreads();
        float4 s0 = *(const float4*)&sm_s[buf][0];
        float4 s1 = *(const float4*)&sm_s[buf][4];
        float S = (s0.x + s0.y) + (s0.z + s0.w)
                + (s1.x + s1.y) + (s1.z + s1.w);
        scale = __fdividef(1.0f, S);                 // onehot_j = e[j]*scale
    }

    // fold in last step's onehot and write out
    #pragma unroll
    for (int j = 0; j < EPT; ++j)
        orow[tid + j * NTHREADS] = acc[j] + e[j] * scale;
}

extern "C" void kernel_launch(void* const* d_in, const int* in_sizes, int n_in,
                              void* d_out, int out_size)
{
    const float* att = (const float*)d_in[0];
    const float* uni = (const float*)d_in[1];
    const int*   kp  = (const int*)d_in[2];
    float* out = (float*)d_out;

    const int B = in_sizes[0] / NNODES;   // 128
    sampler_topk_kernel<<<B, NTHREADS>>>(att, uni, kp, out);
}

// round 6
// speedup vs baseline: 2.5617x; 1.3969x over previous
#include <cuda_runtime.h>
#include <math.h>

// Sampler: Gumbel-keys relaxed top-k. khot = sum_{t=1..k} softmax(att_g_t),
// att_g_{t+1} = att_g_t + log(max(1 - onehot_t, eps)).
// One CTA per row (B=128 rows, n=1024), state in registers.
// KEY IDENTITIES:
//  (1) att_g monotone non-increasing -> fixed softmax shift M0 (computed once).
//  (2) exp(att_g + log(mask)) = e * mask -> maintain unnormalized numerators:
//      r = e/S; acc += r; e <- max(e - r*e, 0).  ZERO log/exp in the k-loop;
//      the only MUFU per step is one RCP.
// Warp sum via 5-level shfl butterfly (redux.sync.f32 unsupported on target).

#define NTHREADS 256
#define NWARPS   (NTHREADS / 32)
#define NNODES   1024
#define EPT      (NNODES / NTHREADS)   // 4
#define EPS_F    1.1754943508222875e-38f  // np.finfo(float32).tiny
#define LOG2E    1.4426950408889634f

__device__ __forceinline__ float ex2_approx(float x) {
    float r; asm("ex2.approx.f32 %0, %1;" : "=f"(r) : "f"(x)); return r;
}

__global__ __launch_bounds__(NTHREADS, 1)
void sampler_topk_kernel(const float* __restrict__ att,
                         const float* __restrict__ uni,
                         const int*  __restrict__ kptr,
                         float* __restrict__ out)
{
    __shared__ __align__(16) float sm_s[2][NWARPS];  // double-buffered sums
    __shared__ __align__(16) float sm_m[NWARPS];     // init-time max only

    const int row  = blockIdx.x;
    const int tid  = threadIdx.x;
    const int lane = tid & 31;
    const int warp = tid >> 5;
    const int k    = *kptr;

    const float* __restrict__ arow = att + row * NNODES;
    const float* __restrict__ urow = uni + row * NNODES;
    float*       __restrict__ orow = out + row * NNODES;

    float b[EPT], e[EPT], acc[EPT];

    // Gumbel init in log2 domain: b = (att - log(-log(u+eps))) * log2(e)
    float m = -3.402823466e38f;
    #pragma unroll
    for (int j = 0; j < EPT; ++j) {
        const int idx = tid + j * NTHREADS;          // coalesced
        float u = urow[idx];
        b[j] = (arow[idx] - logf(-logf(u + EPS_F))) * LOG2E;
        m = fmaxf(m, b[j]);
        acc[j] = 0.0f;
    }
    // one-time block max M0 (valid shift forever: logits only decrease)
    #pragma unroll
    for (int o = 16; o > 0; o >>= 1)
        m = fmaxf(m, __shfl_xor_sync(0xffffffffu, m, o));
    if (lane == 0) sm_m[warp] = m;
    __syncthreads();
    {
        float4 m0 = *(const float4*)&sm_m[0];
        float4 m1 = *(const float4*)&sm_m[4];
        float M = fmaxf(fmaxf(fmaxf(m0.x, m0.y), fmaxf(m0.z, m0.w)),
                        fmaxf(fmaxf(m1.x, m1.y), fmaxf(m1.z, m1.w)));
        #pragma unroll
        for (int j = 0; j < EPT; ++j)
            e[j] = ex2_approx(b[j] - M);             // unnormalized numerators
    }

    float scale = 0.0f;   // onehot_{-1} = 0  (first iteration: r = 0)

    for (int t = 0; t < k; ++t) {
        // fold previous onehot into acc and mask e (pure FMA pipe)
        float s = 0.0f;
        #pragma unroll
        for (int j = 0; j < EPT; ++j) {
            float r = e[j] * scale;                  // onehot_{t-1}
            acc[j] += r;
            e[j] = fmaxf(__fmaf_rn(-r, e[j], e[j]), 0.0f);  // e*(1-r), clamped
            s += e[j];
        }
        // warp sum: 5-level butterfly (all lanes get warp total)
        #pragma unroll
        for (int o = 16; o > 0; o >>= 1)
            s += __shfl_xor_sync(0xffffffffu, s, o);
        const int buf = t & 1;
        if (lane == 0) sm_s[buf][warp] = s;
        __syncthreads();
        float4 s0 = *(const float4*)&sm_s[buf][0];
        float4 s1 = *(const float4*)&sm_s[buf][4];
        float S = ((s0.x + s0.y) + (s0.z + s0.w))
                + ((s1.x + s1.y) + (s1.z + s1.w));
        scale = __fdividef(1.0f, S);                 // the only MUFU per step
    }

    // fold in final step's onehot and write out
    #pragma unroll
    for (int j = 0; j < EPT; ++j)
        orow[tid + j * NTHREADS] = acc[j] + e[j] * scale;
}

extern "C" void kernel_launch(void* const* d_in, const int* in_sizes, int n_in,
                              void* d_out, int out_size)
{
    const float* att = (const float*)d_in[0];
    const float* uni = (const float*)d_in[1];
    const int*   kp  = (const int*)d_in[2];
    float* out = (float*)d_out;

    const int B = in_sizes[0] / NNODES;   // 128
    sampler_topk_kernel<<<B, NTHREADS>>>(att, uni, kp, out);
}

// round 7
// speedup vs baseline: 3.2993x; 1.2879x over previous
#include <cuda_runtime.h>
#include <math.h>

// Sampler: Gumbel-keys relaxed top-k. khot = sum_{t=1..k} softmax(att_g_t),
// att_g_{t+1} = att_g_t + log(max(1 - onehot_t, eps)).
// One CTA per row (B=128 rows, n=1024), state in registers. Latency-chain
// bound -> minimize SYNCHRONIZATIONS, not work:
//  (1) fixed softmax shift M0 (logits monotone non-increasing), computed once.
//  (2) unnormalized numerators: oh = e/S; acc += oh; e <- e*(1-oh).
//  (3) STEP FUSION: S' = sum e(1-e/S) = S - Q/S with Q = sum e^2. Reduce
//      (S,Q) in ONE barrier round-trip (interleaved butterflies), then run
//      TWO update rounds (scaleA = 1/S, scaleB = 1/S'). 308 syncs for 615
//      steps. Recurrence error is one-shot: next sync re-reduces true S.

#define NTHREADS 256
#define NWARPS   (NTHREADS / 32)
#define NNODES   1024
#define EPT      (NNODES / NTHREADS)   // 4
#define EPS_F    1.1754943508222875e-38f  // np.finfo(float32).tiny
#define LOG2E    1.4426950408889634f

__device__ __forceinline__ float ex2_approx(float x) {
    float r; asm("ex2.approx.f32 %0, %1;" : "=f"(r) : "f"(x)); return r;
}
__device__ __forceinline__ float rcp_approx(float x) {
    float r; asm("rcp.approx.f32 %0, %1;" : "=f"(r) : "f"(x)); return r;
}

__global__ __launch_bounds__(NTHREADS, 1)
void sampler_topk_kernel(const float* __restrict__ att,
                         const float* __restrict__ uni,
                         const int*  __restrict__ kptr,
                         float* __restrict__ out)
{
    // (s,q) per warp, double-buffered; single barrier per sync is race-free
    __shared__ __align__(16) float2 sm_sq[2][NWARPS];
    __shared__ __align__(16) float  sm_m[NWARPS];

    const int row  = blockIdx.x;
    const int tid  = threadIdx.x;
    const int lane = tid & 31;
    const int warp = tid >> 5;
    const int k    = *kptr;

    const float* __restrict__ arow = att + row * NNODES;
    const float* __restrict__ urow = uni + row * NNODES;
    float*       __restrict__ orow = out + row * NNODES;

    float b[EPT], e[EPT], acc[EPT];

    // Gumbel init in log2 domain: b = (att - log(-log(u+eps))) * log2(e)
    float m = -3.402823466e38f;
    #pragma unroll
    for (int j = 0; j < EPT; ++j) {
        const int idx = tid + j * NTHREADS;          // coalesced
        float u = urow[idx];
        b[j] = (arow[idx] - logf(-logf(u + EPS_F))) * LOG2E;
        m = fmaxf(m, b[j]);
        acc[j] = 0.0f;
    }
    // one-time block max M0 (valid shift forever: logits only decrease)
    #pragma unroll
    for (int o = 16; o > 0; o >>= 1)
        m = fmaxf(m, __shfl_xor_sync(0xffffffffu, m, o));
    if (lane == 0) sm_m[warp] = m;
    __syncthreads();
    {
        float4 m0 = *(const float4*)&sm_m[0];
        float4 m1 = *(const float4*)&sm_m[4];
        float M = fmaxf(fmaxf(fmaxf(m0.x, m0.y), fmaxf(m0.z, m0.w)),
                        fmaxf(fmaxf(m1.x, m1.y), fmaxf(m1.z, m1.w)));
        #pragma unroll
        for (int j = 0; j < EPT; ++j)
            e[j] = ex2_approx(b[j] - M);             // unnormalized numerators
    }

    const int nsync = (k + 1) >> 1;                  // 308 for k=615
    int steps_left = k;

    for (int it = 0; it < nsync; ++it) {
        // ---- reduce (S, Q) from current e: interleaved butterflies ----
        float s = (e[0] + e[1]) + (e[2] + e[3]);
        float q = __fmaf_rn(e[0], e[0], e[1] * e[1])
                + __fmaf_rn(e[2], e[2], e[3] * e[3]);
        #pragma unroll
        for (int o = 16; o > 0; o >>= 1) {
            s += __shfl_xor_sync(0xffffffffu, s, o);
            q += __shfl_xor_sync(0xffffffffu, q, o);
        }
        const int buf = it & 1;
        if (lane == 0) sm_sq[buf][warp] = make_float2(s, q);
        __syncthreads();
        const float4* sq = (const float4*)&sm_sq[buf][0];  // (s0,q0,s1,q1)...
        float4 v0 = sq[0], v1 = sq[1], v2 = sq[2], v3 = sq[3];
        float S = ((v0.x + v0.z) + (v1.x + v1.z))
                + ((v2.x + v2.z) + (v3.x + v3.z));
        float Q = ((v0.y + v0.w) + (v1.y + v1.w))
                + ((v2.y + v2.w) + (v3.y + v3.w));

        float scaleA = rcp_approx(S);
        // ---- round A ----
        #pragma unroll
        for (int j = 0; j < EPT; ++j) {
            float oh = e[j] * scaleA;
            acc[j] = __fmaf_rn(e[j], scaleA, acc[j]);
            e[j]   = __fmaf_rn(-oh, e[j], e[j]);     // e*(1-oh)
        }
        if (steps_left >= 2) {
            // S' = S - Q/S (guarded), overlaps round A above
            float Sp = __fmaf_rn(-Q, scaleA, S);
            Sp = fmaxf(Sp, S * 1e-6f);
            float scaleB = rcp_approx(Sp);
            // ---- round B ----
            #pragma unroll
            for (int j = 0; j < EPT; ++j) {
                float oh = e[j] * scaleB;
                acc[j] = __fmaf_rn(e[j], scaleB, acc[j]);
                e[j]   = __fmaf_rn(-oh, e[j], e[j]);
            }
            steps_left -= 2;
        } else {
            steps_left -= 1;
        }
    }

    #pragma unroll
    for (int j = 0; j < EPT; ++j)
        orow[tid + j * NTHREADS] = acc[j];
}

extern "C" void kernel_launch(void* const* d_in, const int* in_sizes, int n_in,
                              void* d_out, int out_size)
{
    const float* att = (const float*)d_in[0];
    const float* uni = (const float*)d_in[1];
    const int*   kp  = (const int*)d_in[2];
    float* out = (float*)d_out;

    const int B = in_sizes[0] / NNODES;   // 128
    sampler_topk_kernel<<<B, NTHREADS>>>(att, uni, kp, out);
}